// round 6
// baseline (speedup 1.0000x reference)
#include <cuda_runtime.h>

// MeshFit update_points_feat: per-class exact kNN (K=3) + softmax-weighted
// feature gather. C=4, N=4096, M=4096, D=32. Output (1, C*M, D) float32.
//
// R6: exact uniform-grid kNN. Kernel 1 bins each class's 4096 points into a
// 16x16 (x,y) grid stored in __device__ scratch. Kernel 2: one WARP per
// query; stages the binned class into smem, scans cells in expanding
// Chebyshev rings, stops when min-over-lanes(local d2) < dmin^2 of the
// unscanned region (lossless: every lane's local d2 >= true d2, and strict
// '<' means skipped points are strictly farther than the true 3rd-NN).
// Distance formula bitwise-identical to the R4/R5 passing kernels; all
// selection uses lexicographic (d, idx) -> exact jax.lax.top_k semantics.

#define CC   4
#define NV   4096
#define MV   4096
#define DF   32
#define GW   16                 // grid cells per axis
#define NCELL (GW * GW)
#define CELLW (1.0f / GW)

__device__ float4 g_binned[CC][NV];        // (x, y, z, idx-as-float), bin order
__device__ int    g_cellStart[CC][NCELL + 1];

__device__ __forceinline__ void lex_insert(float t, int ti,
                                           float& d0, float& d1, float& d2,
                                           int& i0, int& i1, int& i2)
{
    if (t < d2 || (t == d2 && ti < i2)) {
        d2 = t; i2 = ti;
        if (d2 < d1 || (d2 == d1 && i2 < i1)) {
            float td = d1; d1 = d2; d2 = td;
            int   tn = i1; i1 = i2; i2 = tn;
        }
        if (d1 < d0 || (d1 == d0 && i1 < i0)) {
            float td = d0; d0 = d1; d1 = td;
            int   tn = i0; i0 = i1; i1 = tn;
        }
    }
}

// ---------------- Kernel 1: bin points per class ----------------
__global__ void __launch_bounds__(1024, 1)
bin_kernel(const float* __restrict__ verts)
{
    __shared__ int counts[NCELL];
    __shared__ int offs[NCELL];
    const int c   = blockIdx.x;
    const int tid = threadIdx.x;

    if (tid < NCELL) counts[tid] = 0;
    __syncthreads();

    const float* vc = verts + (size_t)c * NV * 3;
    for (int n = tid; n < NV; n += 1024) {
        const float x = vc[3 * n + 0], y = vc[3 * n + 1];
        int cx = (int)(x * GW); cx = cx < 0 ? 0 : (cx > GW - 1 ? GW - 1 : cx);
        int cy = (int)(y * GW); cy = cy < 0 ? 0 : (cy > GW - 1 ? GW - 1 : cy);
        atomicAdd(&counts[cy * GW + cx], 1);
    }
    __syncthreads();

    if (tid == 0) {
        int run = 0;
        for (int i = 0; i < NCELL; ++i) {
            g_cellStart[c][i] = run;
            offs[i] = run;
            run += counts[i];
        }
        g_cellStart[c][NCELL] = run;   // == NV
    }
    __syncthreads();

    for (int n = tid; n < NV; n += 1024) {
        const float x = vc[3 * n + 0], y = vc[3 * n + 1], z = vc[3 * n + 2];
        int cx = (int)(x * GW); cx = cx < 0 ? 0 : (cx > GW - 1 ? GW - 1 : cx);
        int cy = (int)(y * GW); cy = cy < 0 ? 0 : (cy > GW - 1 ? GW - 1 : cy);
        const int slot = atomicAdd(&offs[cy * GW + cx], 1);
        g_binned[c][slot] = make_float4(x, y, z, __int_as_float(n));
    }
}

// ---------------- Kernel 2: warp-per-query ring search ----------------
__global__ void __launch_bounds__(1024, 1)
query_kernel(const float* __restrict__ feat,
             const float* __restrict__ nverts,
             float* __restrict__ out)
{
    extern __shared__ char smem[];
    float4* spts   = (float4*)smem;                    // NV * 16 = 64 KB
    int*    sStart = (int*)(smem + NV * sizeof(float4)); // NCELL+1 ints

    const int tid  = threadIdx.x;
    const int warp = tid >> 5;
    const int lane = tid & 31;

    const int Q = blockIdx.x * 32 + warp;    // global query id [0, C*MV)
    const int c = Q >> 12;                   // class (4096 queries per class)
    const int m = Q & (MV - 1);

    // Stage this class's binned points + cell table into shared memory.
    for (int i = tid; i < NV; i += 1024) spts[i] = g_binned[c][i];
    for (int i = tid; i < NCELL + 1; i += 1024) sStart[i] = g_cellStart[c][i];
    __syncthreads();

    const float* q = nverts + ((size_t)c * MV + m) * 3;
    const float qx = q[0], qy = q[1], qz = q[2];
    int cx = (int)(qx * GW); cx = cx < 0 ? 0 : (cx > GW - 1 ? GW - 1 : cx);
    int cy = (int)(qy * GW); cy = cy < 0 ? 0 : (cy > GW - 1 ? GW - 1 : cy);

    float d0 = 3.402823466e38f, d1 = 3.402823466e38f, d2 = 3.402823466e38f;
    int   i0 = 0x7fffffff, i1 = 0x7fffffff, i2 = 0x7fffffff;

    for (int r = 0; r < GW; ++r) {
        // Process all cells at Chebyshev ring r around (cx, cy).
        for (int iy = -r; iy <= r; ++iy) {
            const int Y = cy + iy;
            if (Y < 0 || Y > GW - 1) continue;
            const bool edge_y = (iy == -r) || (iy == r);
            const int x_lo = edge_y ? (cx - r) : (cx - r);
            // enumerate: full row if edge_y, else just the two side columns
            for (int ix = -r; ix <= r; ++ix) {
                if (!edge_y && ix != -r && ix != r) continue;
                const int X = cx + ix;
                if (X < 0 || X > GW - 1) continue;
                const int cell = Y * GW + X;
                const int s = sStart[cell], e = sStart[cell + 1];
                for (int slot = s + lane; slot < e; slot += 32) {
                    const float4 p = spts[slot];
                    const float dx = qx - p.x;
                    const float dy = qy - p.y;
                    const float dz = qz - p.z;
                    const float t = fmaf(dz, dz, fmaf(dy, dy, dx * dx));
                    lex_insert(t, __float_as_int(p.w), d0, d1, d2, i0, i1, i2);
                }
            }
            (void)x_lo;
        }
        // Stopping bound: unscanned points lie outside the covered square
        // x in [(cx-r)w, (cx+r+1)w], y likewise (clipped at domain edges).
        const float sL = (cx - r <= 0)      ? 1e30f : qx - (cx - r) * CELLW;
        const float sR = (cx + r >= GW - 1) ? 1e30f : (cx + r + 1) * CELLW - qx;
        const float sB = (cy - r <= 0)      ? 1e30f : qy - (cy - r) * CELLW;
        const float sT = (cy + r >= GW - 1) ? 1e30f : (cy + r + 1) * CELLW - qy;
        const float dmin = fminf(fminf(sL, sR), fminf(sB, sT));
        // B = min over lanes of local d2  (>= true d2 of the union)
        float B = d2;
#pragma unroll
        for (int off = 1; off < 32; off <<= 1)
            B = fminf(B, __shfl_xor_sync(0xffffffffu, B, off));
        if (B < dmin * dmin) break;   // strict: skipped points strictly farther
    }

    // Full-warp butterfly merge; lexicographic (d, idx) = exact top_k order.
#pragma unroll
    for (int off = 1; off < 32; off <<= 1) {
        const float pd0 = __shfl_xor_sync(0xffffffffu, d0, off);
        const float pd1 = __shfl_xor_sync(0xffffffffu, d1, off);
        const float pd2 = __shfl_xor_sync(0xffffffffu, d2, off);
        const int   pi0 = __shfl_xor_sync(0xffffffffu, i0, off);
        const int   pi1 = __shfl_xor_sync(0xffffffffu, i1, off);
        const int   pi2 = __shfl_xor_sync(0xffffffffu, i2, off);
        lex_insert(pd0, pi0, d0, d1, d2, i0, i1, i2);
        lex_insert(pd1, pi1, d0, d1, d2, i0, i1, i2);
        lex_insert(pd2, pi2, d0, d1, d2, i0, i1, i2);
    }

    // Global column indices + exact merge of constant-1.0 off-block fillers.
    const int base = c * NV;
    int g0 = base + i0, g1 = base + i1, g2 = base + i2;
    const int fbase = (c == 0) ? NV : 0;
#pragma unroll
    for (int k = 0; k < 3; ++k)
        lex_insert(1.0f, fbase + k, d0, d1, d2, g0, g1, g2);

    // softmax(-d), max-subtracted (d0 smallest).
    const float e1 = expf(d0 - d1);
    const float e2 = expf(d0 - d2);
    const float inv = 1.0f / (1.0f + e1 + e2);
    const float w0 = inv, w1 = e1 * inv, w2 = e2 * inv;

    // Lanes 0..7 write the 8 float4 chunks of the D=32 output row.
    if (lane < DF / 4) {
        const float4 a  = ((const float4*)(feat + (size_t)g0 * DF))[lane];
        const float4 b  = ((const float4*)(feat + (size_t)g1 * DF))[lane];
        const float4 cv = ((const float4*)(feat + (size_t)g2 * DF))[lane];
        float4 rr;
        rr.x = w0 * a.x + w1 * b.x + w2 * cv.x;
        rr.y = w0 * a.y + w1 * b.y + w2 * cv.y;
        rr.z = w0 * a.z + w1 * b.z + w2 * cv.z;
        rr.w = w0 * a.w + w1 * b.w + w2 * cv.w;
        ((float4*)(out + ((size_t)c * MV + m) * DF))[lane] = rr;
    }
}

extern "C" void kernel_launch(void* const* d_in, const int* in_sizes, int n_in,
                              void* d_out, int out_size)
{
    const float* feat   = (const float*)d_in[0];  // (1, C*N, D)
    const float* verts  = (const float*)d_in[1];  // (C, N, 3)
    const float* nverts = (const float*)d_in[2];  // (C, M, 3)
    float* out = (float*)d_out;                   // (1, C*M, D)

    bin_kernel<<<CC, 1024>>>(verts);

    const int smem = NV * sizeof(float4) + (NCELL + 1) * sizeof(int);
    cudaFuncSetAttribute(query_kernel,
                         cudaFuncAttributeMaxDynamicSharedMemorySize, smem);
    query_kernel<<<(CC * MV) / 32, 1024, smem>>>(feat, nverts, out);
}

// round 7
// speedup vs baseline: 1.1386x; 1.1386x over previous
#include <cuda_runtime.h>

// MeshFit update_points_feat: per-class exact kNN (K=3) + softmax-weighted
// feature gather. C=4, N=4096, M=4096, D=32. Output (1, C*M, D) float32.
//
// R7: uniform 16x16 grid + THREAD-per-query (queries counting-sorted by cell
// so warps are spatially coherent), per-thread expanding-ring exact search
// with per-thread stop bound. ~200 candidate points per query instead of
// 4096 -> ~1M warp-instructions total. All selection lexicographic (d, idx)
// => exact jax.lax.top_k semantics independent of bin/scan order.

#define CC    4
#define NV    4096
#define MV    4096
#define DF    32
#define GW    16
#define NCELL (GW * GW)
#define CELLW (1.0f / GW)
#define QTB   128              // queries (threads) per block
#define NBLK  ((CC * MV) / QTB)  // 128 blocks

__device__ float4 g_binned[CC][NV];          // (x, y, z, idx) in bin order
__device__ int    g_cellStart[CC][NCELL + 1];
__device__ int    g_qorder[CC][MV];          // query ids sorted by cell

__device__ __forceinline__ int clampg(int v) {
    return v < 0 ? 0 : (v > GW - 1 ? GW - 1 : v);
}

__device__ __forceinline__ void lex_insert(float t, int ti,
                                           float& d0, float& d1, float& d2,
                                           int& i0, int& i1, int& i2)
{
    if (t < d2 || (t == d2 && ti < i2)) {
        d2 = t; i2 = ti;
        if (d2 < d1 || (d2 == d1 && i2 < i1)) {
            float td = d1; d1 = d2; d2 = td;
            int   tn = i1; i1 = i2; i2 = tn;
        }
        if (d1 < d0 || (d1 == d0 && i1 < i0)) {
            float td = d0; d0 = d1; d1 = td;
            int   tn = i0; i0 = i1; i1 = tn;
        }
    }
}

// ---------------- Kernel 1: bin points AND sort queries (8 blocks) --------
__global__ void __launch_bounds__(1024, 1)
prep_kernel(const float* __restrict__ verts,
            const float* __restrict__ nverts)
{
    __shared__ int counts[NCELL];
    __shared__ int offs[NCELL];
    const int b   = blockIdx.x;
    const int tid = threadIdx.x;

    if (tid < NCELL) counts[tid] = 0;
    __syncthreads();

    if (b < CC) {
        // ---- bin points of class b ----
        const int c = b;
        const float* vc = verts + (size_t)c * NV * 3;
        for (int n = tid; n < NV; n += 1024) {
            const int cx = clampg((int)(vc[3 * n + 0] * GW));
            const int cy = clampg((int)(vc[3 * n + 1] * GW));
            atomicAdd(&counts[cy * GW + cx], 1);
        }
        __syncthreads();
        if (tid == 0) {
            int run = 0;
            for (int i = 0; i < NCELL; ++i) {
                g_cellStart[c][i] = run; offs[i] = run; run += counts[i];
            }
            g_cellStart[c][NCELL] = run;
        }
        __syncthreads();
        for (int n = tid; n < NV; n += 1024) {
            const float x = vc[3 * n + 0], y = vc[3 * n + 1], z = vc[3 * n + 2];
            const int cx = clampg((int)(x * GW));
            const int cy = clampg((int)(y * GW));
            const int slot = atomicAdd(&offs[cy * GW + cx], 1);
            g_binned[c][slot] = make_float4(x, y, z, __int_as_float(n));
        }
    } else {
        // ---- sort queries of class b-CC by cell ----
        const int c = b - CC;
        const float* qc = nverts + (size_t)c * MV * 3;
        for (int m = tid; m < MV; m += 1024) {
            const int cx = clampg((int)(qc[3 * m + 0] * GW));
            const int cy = clampg((int)(qc[3 * m + 1] * GW));
            atomicAdd(&counts[cy * GW + cx], 1);
        }
        __syncthreads();
        if (tid == 0) {
            int run = 0;
            for (int i = 0; i < NCELL; ++i) { offs[i] = run; run += counts[i]; }
        }
        __syncthreads();
        for (int m = tid; m < MV; m += 1024) {
            const int cx = clampg((int)(qc[3 * m + 0] * GW));
            const int cy = clampg((int)(qc[3 * m + 1] * GW));
            const int slot = atomicAdd(&offs[cy * GW + cx], 1);
            g_qorder[c][slot] = m;
        }
    }
}

// ---------------- Kernel 2: thread-per-query ring search ----------------
__global__ void __launch_bounds__(QTB, 3)
query_kernel(const float* __restrict__ feat,
             const float* __restrict__ nverts,
             float* __restrict__ out)
{
    extern __shared__ char smem[];
    float4* spts   = (float4*)smem;                      // 64 KB
    int*    sStart = (int*)(smem + NV * sizeof(float4)); // 257 ints

    const int tid = threadIdx.x;
    const int c    = blockIdx.x >> 5;          // 32 blocks per class
    const int slot = (blockIdx.x & 31) * QTB + tid;

    // Stage this class's binned points + cell table.
    for (int i = tid; i < NV; i += QTB) spts[i] = g_binned[c][i];
    for (int i = tid; i < NCELL + 1; i += QTB) sStart[i] = g_cellStart[c][i];
    __syncthreads();

    const int m = g_qorder[c][slot];
    const float* q = nverts + ((size_t)c * MV + m) * 3;
    const float qx = q[0], qy = q[1], qz = q[2];
    const int cx = clampg((int)(qx * GW));
    const int cy = clampg((int)(qy * GW));

    float d0 = 3.402823466e38f, d1 = 3.402823466e38f, d2 = 3.402823466e38f;
    int   i0 = 0x7fffffff, i1 = 0x7fffffff, i2 = 0x7fffffff;

#pragma unroll 1
    for (int r = 0; r < GW; ++r) {
        const int y0 = cy - r < 0 ? 0 : cy - r;
        const int y1 = cy + r > GW - 1 ? GW - 1 : cy + r;
        const int x0 = cx - r < 0 ? 0 : cx - r;
        const int x1 = cx + r > GW - 1 ? GW - 1 : cx + r;
#pragma unroll 1
        for (int Y = y0; Y <= y1; ++Y) {
            const bool edge_y = (Y == cy - r) || (Y == cy + r);
#pragma unroll 1
            for (int X = x0; X <= x1; ++X) {
                if (!edge_y && X != cx - r && X != cx + r) continue;
                const int cell = Y * GW + X;
                const int s = sStart[cell], e = sStart[cell + 1];
#pragma unroll 2
                for (int p = s; p < e; ++p) {
                    const float4 pt = spts[p];
                    const float dx = qx - pt.x;
                    const float dy = qy - pt.y;
                    const float dz = qz - pt.z;
                    const float t = fmaf(dz, dz, fmaf(dy, dy, dx * dx));
                    lex_insert(t, __float_as_int(pt.w), d0, d1, d2, i0, i1, i2);
                }
            }
        }
        // Per-thread stop: unscanned cells lie outside the covered square.
        const float sL = (cx - r <= 0)      ? 1e30f : qx - (cx - r) * CELLW;
        const float sR = (cx + r >= GW - 1) ? 1e30f : (cx + r + 1) * CELLW - qx;
        const float sB = (cy - r <= 0)      ? 1e30f : qy - (cy - r) * CELLW;
        const float sT = (cy + r >= GW - 1) ? 1e30f : (cy + r + 1) * CELLW - qy;
        const float dmin = fminf(fminf(sL, sR), fminf(sB, sT));
        // 1e-5 relative safety margin vs fp rounding of the bound.
        if (d2 * 1.00001f < dmin * dmin) break;
    }

    // Global column indices + exact merge of constant-1.0 off-block fillers.
    const int base = c * NV;
    int g0 = base + i0, g1 = base + i1, g2 = base + i2;
    const int fbase = (c == 0) ? NV : 0;
#pragma unroll
    for (int k = 0; k < 3; ++k)
        lex_insert(1.0f, fbase + k, d0, d1, d2, g0, g1, g2);

    // softmax(-d), max-subtracted (d0 smallest).
    const float e1 = expf(d0 - d1);
    const float e2 = expf(d0 - d2);
    const float inv = 1.0f / (1.0f + e1 + e2);
    const float w0 = inv, w1 = e1 * inv, w2 = e2 * inv;

    // Weighted gather: this thread writes its query's full 32-float row.
    const float4* f0 = (const float4*)(feat + (size_t)g0 * DF);
    const float4* f1 = (const float4*)(feat + (size_t)g1 * DF);
    const float4* f2 = (const float4*)(feat + (size_t)g2 * DF);
    float4* o = (float4*)(out + ((size_t)c * MV + m) * DF);
#pragma unroll
    for (int k = 0; k < DF / 4; ++k) {
        const float4 a = f0[k], b = f1[k], cv = f2[k];
        float4 rr;
        rr.x = w0 * a.x + w1 * b.x + w2 * cv.x;
        rr.y = w0 * a.y + w1 * b.y + w2 * cv.y;
        rr.z = w0 * a.z + w1 * b.z + w2 * cv.z;
        rr.w = w0 * a.w + w1 * b.w + w2 * cv.w;
        o[k] = rr;
    }
}

extern "C" void kernel_launch(void* const* d_in, const int* in_sizes, int n_in,
                              void* d_out, int out_size)
{
    const float* feat   = (const float*)d_in[0];  // (1, C*N, D)
    const float* verts  = (const float*)d_in[1];  // (C, N, 3)
    const float* nverts = (const float*)d_in[2];  // (C, M, 3)
    float* out = (float*)d_out;                   // (1, C*M, D)

    prep_kernel<<<2 * CC, 1024>>>(verts, nverts);

    const int smem = NV * sizeof(float4) + (NCELL + 1) * sizeof(int);
    cudaFuncSetAttribute(query_kernel,
                         cudaFuncAttributeMaxDynamicSharedMemorySize, smem);
    query_kernel<<<NBLK, QTB, smem>>>(feat, nverts, out);
}

// round 8
// speedup vs baseline: 1.6742x; 1.4704x over previous
#include <cuda_runtime.h>

// MeshFit update_points_feat: per-class exact kNN (K=3) + softmax-weighted
// feature gather. C=4, N=4096, M=4096, D=32. Output (1, C*M, D) float32.
//
// R8: uniform 16x16 grid, 8 LANES PER QUERY (131072 threads -> 32 warps/SM,
// fixes R7's 1-warp-per-SMSP latency exposure). Lanes stride points within a
// cell; per-ring stop bound B = shfl-min of lane d2 (B >= true d2 => lossless
// skip). Branchless lexicographic top-3 insert (no divergence). Prep kernel
// uses a parallel Hillis-Steele scan. All selection lex (d, idx) => exact
// jax.lax.top_k semantics regardless of bin/scan order.

#define CC    4
#define NV    4096
#define MV    4096
#define DF    32
#define GW    16
#define NCELL (GW * GW)
#define CELLW (1.0f / GW)
#define QL    8                  // lanes per query
#define TB    1024               // threads per block -> 128 queries per block
#define QPB   (TB / QL)          // 128
#define NBLK  ((CC * MV) / QPB)  // 128 blocks

__device__ float4 g_binned[CC][NV];          // (x, y, z, idx) in bin order
__device__ int    g_cellStart[CC][NCELL + 1];
__device__ int    g_qorder[CC][MV];          // query ids sorted by cell

__device__ __forceinline__ int clampg(int v) {
    return v < 0 ? 0 : (v > GW - 1 ? GW - 1 : v);
}

__device__ __forceinline__ bool lex_lt(float t, int n, float d, int i) {
    return (t < d) || (t == d && n < i);
}

// Branchless sorted-top-3 insert with lexicographic (d, idx) order.
__device__ __forceinline__ void bl_insert(float t, int n,
                                          float& d0, float& d1, float& d2,
                                          int& i0, int& i1, int& i2)
{
    const bool c0 = lex_lt(t, n, d0, i0);
    const bool c1 = lex_lt(t, n, d1, i1);
    const bool c2 = lex_lt(t, n, d2, i2);
    d2 = c1 ? d1 : (c2 ? t : d2);  i2 = c1 ? i1 : (c2 ? n : i2);
    d1 = c0 ? d0 : (c1 ? t : d1);  i1 = c0 ? i0 : (c1 ? n : i1);
    d0 = c0 ? t  : d0;             i0 = c0 ? n  : i0;
}

__device__ __forceinline__ void lex_insert(float t, int ti,
                                           float& d0, float& d1, float& d2,
                                           int& i0, int& i1, int& i2)
{
    bl_insert(t, ti, d0, d1, d2, i0, i1, i2);
}

// ---------------- Kernel 1: bin points AND sort queries (8 blocks) --------
__global__ void __launch_bounds__(1024, 1)
prep_kernel(const float* __restrict__ verts,
            const float* __restrict__ nverts)
{
    __shared__ int counts[NCELL];
    __shared__ int scan[NCELL];
    __shared__ int offs[NCELL];
    const int b   = blockIdx.x;
    const int tid = threadIdx.x;
    const int cnt = (b < CC) ? NV : MV;
    const int c   = (b < CC) ? b : b - CC;
    const float* src = (b < CC) ? (verts + (size_t)c * NV * 3)
                                : (nverts + (size_t)c * MV * 3);

    if (tid < NCELL) counts[tid] = 0;
    __syncthreads();

    for (int n = tid; n < cnt; n += 1024) {
        const int cx = clampg((int)(src[3 * n + 0] * GW));
        const int cy = clampg((int)(src[3 * n + 1] * GW));
        atomicAdd(&counts[cy * GW + cx], 1);
    }
    __syncthreads();

    // Parallel inclusive scan (Hillis-Steele) over 256 cells.
    if (tid < NCELL) scan[tid] = counts[tid];
    __syncthreads();
#pragma unroll
    for (int st = 1; st < NCELL; st <<= 1) {
        int v = 0;
        if (tid < NCELL && tid >= st) v = scan[tid - st];
        __syncthreads();
        if (tid < NCELL) scan[tid] += v;
        __syncthreads();
    }
    if (tid < NCELL) {
        const int ex = scan[tid] - counts[tid];   // exclusive prefix
        offs[tid] = ex;
        if (b < CC) g_cellStart[c][tid] = ex;
    }
    if (b < CC && tid == 0) g_cellStart[c][NCELL] = NV;
    __syncthreads();

    if (b < CC) {
        for (int n = tid; n < NV; n += 1024) {
            const float x = src[3 * n + 0], y = src[3 * n + 1], z = src[3 * n + 2];
            const int cx = clampg((int)(x * GW));
            const int cy = clampg((int)(y * GW));
            const int slot = atomicAdd(&offs[cy * GW + cx], 1);
            g_binned[c][slot] = make_float4(x, y, z, __int_as_float(n));
        }
    } else {
        for (int m = tid; m < MV; m += 1024) {
            const int cx = clampg((int)(src[3 * m + 0] * GW));
            const int cy = clampg((int)(src[3 * m + 1] * GW));
            const int slot = atomicAdd(&offs[cy * GW + cx], 1);
            g_qorder[c][slot] = m;
        }
    }
}

// ---------------- Kernel 2: 8-lanes-per-query ring search ----------------
__global__ void __launch_bounds__(TB, 1)
query_kernel(const float* __restrict__ feat,
             const float* __restrict__ nverts,
             float* __restrict__ out)
{
    extern __shared__ char smem[];
    float4* spts   = (float4*)smem;                      // 64 KB
    int*    sStart = (int*)(smem + NV * sizeof(float4)); // 257 ints

    const int tid = threadIdx.x;
    const int lq  = tid & (QL - 1);            // lane role within query group
    const int c    = blockIdx.x >> 5;          // 32 blocks per class
    const int slot = (blockIdx.x & 31) * QPB + (tid >> 3);

    // Stage this class's binned points + cell table.
    for (int i = tid; i < NV; i += TB) spts[i] = g_binned[c][i];
    for (int i = tid; i < NCELL + 1; i += TB) sStart[i] = g_cellStart[c][i];
    __syncthreads();

    const int m = g_qorder[c][slot];
    const float* q = nverts + ((size_t)c * MV + m) * 3;
    const float qx = q[0], qy = q[1], qz = q[2];
    const int cx = clampg((int)(qx * GW));
    const int cy = clampg((int)(qy * GW));

    float d0 = 3.402823466e38f, d1 = 3.402823466e38f, d2 = 3.402823466e38f;
    int   i0 = 0x7fffffff, i1 = 0x7fffffff, i2 = 0x7fffffff;

    bool done = false;
#pragma unroll 1
    for (int r = 0; r < GW; ++r) {
        if (!done) {
            const int y0 = cy - r < 0 ? 0 : cy - r;
            const int y1 = cy + r > GW - 1 ? GW - 1 : cy + r;
            const int x0 = cx - r < 0 ? 0 : cx - r;
            const int x1 = cx + r > GW - 1 ? GW - 1 : cx + r;
#pragma unroll 1
            for (int Y = y0; Y <= y1; ++Y) {
                const bool edge_y = (Y == cy - r) || (Y == cy + r);
#pragma unroll 1
                for (int X = x0; X <= x1; ++X) {
                    if (!edge_y && X != cx - r && X != cx + r) continue;
                    const int cell = Y * GW + X;
                    const int s = sStart[cell], e = sStart[cell + 1];
                    // 8 lanes of this query stride the cell's point list.
                    for (int p = s + lq; p < e; p += QL) {
                        const float4 pt = spts[p];
                        const float dx = qx - pt.x;
                        const float dy = qy - pt.y;
                        const float dz = qz - pt.z;
                        const float t = fmaf(dz, dz, fmaf(dy, dy, dx * dx));
                        bl_insert(t, __float_as_int(pt.w),
                                  d0, d1, d2, i0, i1, i2);
                    }
                }
            }
        }
        // Stop bound: B = min over the 8 lanes of local d2 (>= true d2).
        float B = d2;
#pragma unroll
        for (int off = 1; off < QL; off <<= 1)
            B = fminf(B, __shfl_xor_sync(0xffffffffu, B, off));
        const float sL = (cx - r <= 0)      ? 1e30f : qx - (cx - r) * CELLW;
        const float sR = (cx + r >= GW - 1) ? 1e30f : (cx + r + 1) * CELLW - qx;
        const float sB = (cy - r <= 0)      ? 1e30f : qy - (cy - r) * CELLW;
        const float sT = (cy + r >= GW - 1) ? 1e30f : (cy + r + 1) * CELLW - qy;
        const float dmin = fminf(fminf(sL, sR), fminf(sB, sT));
        done = done || (B * 1.00001f < dmin * dmin);
        if (__all_sync(0xffffffffu, done)) break;
    }

    // Butterfly merge across the 8 lanes; lex (d, idx) = exact top_k order.
#pragma unroll
    for (int off = 1; off < QL; off <<= 1) {
        const float pd0 = __shfl_xor_sync(0xffffffffu, d0, off);
        const float pd1 = __shfl_xor_sync(0xffffffffu, d1, off);
        const float pd2 = __shfl_xor_sync(0xffffffffu, d2, off);
        const int   pi0 = __shfl_xor_sync(0xffffffffu, i0, off);
        const int   pi1 = __shfl_xor_sync(0xffffffffu, i1, off);
        const int   pi2 = __shfl_xor_sync(0xffffffffu, i2, off);
        lex_insert(pd0, pi0, d0, d1, d2, i0, i1, i2);
        lex_insert(pd1, pi1, d0, d1, d2, i0, i1, i2);
        lex_insert(pd2, pi2, d0, d1, d2, i0, i1, i2);
    }

    // Global column indices + exact merge of constant-1.0 off-block fillers.
    const int base = c * NV;
    int g0 = base + i0, g1 = base + i1, g2 = base + i2;
    const int fbase = (c == 0) ? NV : 0;
#pragma unroll
    for (int k = 0; k < 3; ++k)
        lex_insert(1.0f, fbase + k, d0, d1, d2, g0, g1, g2);

    // softmax(-d), max-subtracted (d0 smallest).
    const float e1 = expf(d0 - d1);
    const float e2 = expf(d0 - d2);
    const float inv = 1.0f / (1.0f + e1 + e2);
    const float w0 = inv, w1 = e1 * inv, w2 = e2 * inv;

    // All 8 lanes hold the identical top-3; each writes one float4 chunk.
    const float4 a  = ((const float4*)(feat + (size_t)g0 * DF))[lq];
    const float4 b  = ((const float4*)(feat + (size_t)g1 * DF))[lq];
    const float4 cv = ((const float4*)(feat + (size_t)g2 * DF))[lq];
    float4 rr;
    rr.x = w0 * a.x + w1 * b.x + w2 * cv.x;
    rr.y = w0 * a.y + w1 * b.y + w2 * cv.y;
    rr.z = w0 * a.z + w1 * b.z + w2 * cv.z;
    rr.w = w0 * a.w + w1 * b.w + w2 * cv.w;
    ((float4*)(out + ((size_t)c * MV + m) * DF))[lq] = rr;
}

extern "C" void kernel_launch(void* const* d_in, const int* in_sizes, int n_in,
                              void* d_out, int out_size)
{
    const float* feat   = (const float*)d_in[0];  // (1, C*N, D)
    const float* verts  = (const float*)d_in[1];  // (C, N, 3)
    const float* nverts = (const float*)d_in[2];  // (C, M, 3)
    float* out = (float*)d_out;                   // (1, C*M, D)

    prep_kernel<<<2 * CC, 1024>>>(verts, nverts);

    const int smem = NV * sizeof(float4) + (NCELL + 1) * sizeof(int);
    cudaFuncSetAttribute(query_kernel,
                         cudaFuncAttributeMaxDynamicSharedMemorySize, smem);
    query_kernel<<<NBLK, TB, smem>>>(feat, nverts, out);
}